// round 6
// baseline (speedup 1.0000x reference)
#include <cuda_runtime.h>
#include <cstdint>

#define NBINS   8192
#define BDIM    4          // batch (fixed for this problem)
#define RMAX    7
#define NC      72         // chunks per batch image -> hist grid = 4*72 = 288
#define THREADS 1024
#define SEGS    16         // merge segments per (r,b)
#define MTHR    64

// Scratch (static device globals: allocation-free rule)
__device__ int    g_part16[BDIM * NC * RMAX * (NBINS / 2)]; // packed int16 pairs
__device__ int    g_merged[RMAX * BDIM * NBINS];
__device__ int    g_cnt[BDIM * NC * RMAX];
__device__ double g_pnum[RMAX * BDIM];
__device__ int    g_pden[RMAX * BDIM];
__device__ int    g_ticket = 0;                             // self-resetting

__device__ __forceinline__ int binf(float x) {
    int k = __float2int_rz(x * (float)NBINS);
    return min(max(k, 0), NBINS - 1);
}

// Packed-bin update helpers: bin k lives in word k>>1, half k&1 (bias 0x8000).
__device__ __forceinline__ void upd(int* h, int pbin, int qbin) {
    atomicAdd(h + (pbin >> 1),   1 << ((pbin & 1) << 4));
    atomicAdd(h + (qbin >> 1), -(1 << ((qbin & 1) << 4)));
}

// One CTA: RR signed histograms (biased-int16-packed), one chunk of one image.
// 2 CTAs/SM (96 KB packed smem, regs capped at 32).
template <int RR>
__global__ void __launch_bounds__(THREADS, 2)
hist_kernel(const float* __restrict__ pred,
            const float* __restrict__ tgt,
            const int*   __restrict__ mask,   // bool serialized as int32, [R,B,V]
            int V, int CH, int BV)
{
    extern __shared__ int sh[];               // RR * NBINS/2 packed counters
    __shared__ int scnt[RR];

    const int t = threadIdx.x;
    const int PACK = RR * (NBINS / 2);
    #pragma unroll
    for (int j = t; j < PACK; j += THREADS) sh[j] = (int)0x80008000u;

    const int cid = blockIdx.x;
    const int b   = cid & (BDIM - 1);
    const int c   = cid >> 2;

    const float* pp = pred + (size_t)b * V;
    const float* gp = tgt  + (size_t)b * V;
    const int*   mp = mask + (size_t)b * V;

    const int start = c * CH;
    const int end   = min(V, start + CH);

    unsigned cntA = 0, cntB = 0;              // 10-bit fields, 3 ROIs each
    __syncthreads();

    for (int off = start + t * 4; off < end; off += THREADS * 4) {
        float4 pv = __ldcs(reinterpret_cast<const float4*>(pp + off));
        float4 gv = __ldcs(reinterpret_cast<const float4*>(gp + off));
        int p0 = binf(pv.x), p1 = binf(pv.y), p2 = binf(pv.z), p3 = binf(pv.w);
        int q0 = binf(gv.x), q1 = binf(gv.y), q2 = binf(gv.z), q3 = binf(gv.w);

        const int* m = mp + off;
        #pragma unroll
        for (int r = 0; r < RR; r++) {
            int4 mv = __ldcs(reinterpret_cast<const int4*>(m));
            m += BV;
            int* h = sh + r * (NBINS / 2);
            const unsigned inc = (r < 3) ? (1u << (10 * r)) : (1u << (10 * (r - 3)));
            if (mv.x) { upd(h, p0, q0); if (r < 3) cntA += inc; else cntB += inc; }
            if (mv.y) { upd(h, p1, q1); if (r < 3) cntA += inc; else cntB += inc; }
            if (mv.z) { upd(h, p2, q2); if (r < 3) cntA += inc; else cntB += inc; }
            if (mv.w) { upd(h, p3, q3); if (r < 3) cntA += inc; else cntB += inc; }
        }
    }
    __syncthreads();
    if (t < RR) scnt[t] = 0;

    // flush: un-bias both halves with one XOR; format matches merge (int16 pairs)
    int* out = g_part16 + (size_t)cid * PACK;
    #pragma unroll
    for (int j = t; j < PACK; j += THREADS) out[j] = sh[j] ^ (int)0x80008000u;
    __syncthreads();

    #pragma unroll
    for (int r = 0; r < RR; r++) {
        int v = (int)(((r < 3 ? cntA >> (10 * r) : cntB >> (10 * (r - 3)))) & 1023u);
        #pragma unroll
        for (int d = 16; d; d >>= 1) v += __shfl_down_sync(0xffffffffu, v, d);
        if ((t & 31) == 0 && v) atomicAdd(&scnt[r], v);
    }
    __syncthreads();
    if (t < RR) g_cnt[cid * RR + t] = scnt[t];
}

// grid = RB * SEGS, 64 thr: sum NC packed partials for one 512-bin segment.
__global__ void __launch_bounds__(MTHR)
merge_kernel(int R, int PACKN)                // PACKN = R*NBINS/2 ints per cid
{
    int g   = blockIdx.x;
    int seg = g & (SEGS - 1);
    int rb  = g >> 4;                         // SEGS == 16
    int r   = rb >> 2;                        // BDIM == 4
    int b   = rb & 3;
    int t   = threadIdx.x;

    const int* base = g_part16 + r * (NBINS / 2) + seg * (NBINS / (2 * SEGS)) + t * 4;
    int a0 = 0, a1 = 0, a2 = 0, a3 = 0, a4 = 0, a5 = 0, a6 = 0, a7 = 0;
    #pragma unroll 4
    for (int c = 0; c < NC; c++) {
        int4 v = *reinterpret_cast<const int4*>(base + (size_t)(c * BDIM + b) * PACKN);
        a0 += (int)(short)v.x; a1 += v.x >> 16;
        a2 += (int)(short)v.y; a3 += v.y >> 16;
        a4 += (int)(short)v.z; a5 += v.z >> 16;
        a6 += (int)(short)v.w; a7 += v.w >> 16;
    }
    int* o = g_merged + (size_t)rb * NBINS + seg * (NBINS / SEGS) + t * 8;
    *reinterpret_cast<int4*>(o)     = make_int4(a0, a1, a2, a3);
    *reinterpret_cast<int4*>(o + 4) = make_int4(a4, a5, a6, a7);
}

// One CTA per (r,b): prefix-scan 8192 bins, sum |cum|; last CTA finalizes.
__global__ void __launch_bounds__(THREADS, 1)
scan_kernel(float* __restrict__ outp, int R, int RB)
{
    __shared__ int wsum[33];
    __shared__ long long wacc[32];
    __shared__ int sden;

    int rb = blockIdx.x;
    int b  = rb & 3;
    int t  = threadIdx.x, lane = t & 31, w = t >> 5;

    const int* m = g_merged + (size_t)rb * NBINS + t * 8;
    int4 v0 = *reinterpret_cast<const int4*>(m);
    int4 v1 = *reinterpret_cast<const int4*>(m + 4);
    int local = v0.x + v0.y + v0.z + v0.w + v1.x + v1.y + v1.z + v1.w;

    int x = local;                            // warp inclusive scan
    #pragma unroll
    for (int d = 1; d < 32; d <<= 1) {
        int y = __shfl_up_sync(0xffffffffu, x, d);
        if (lane >= d) x += y;
    }
    if (lane == 31) wsum[w + 1] = x;
    if (t == 0) { sden = 0; wsum[0] = 0; }
    __syncthreads();
    if (t == 0)
        for (int i = 1; i < 32; i++) wsum[i + 1] += wsum[i];
    __syncthreads();

    int cum = wsum[w] + x - local;            // exclusive prefix for this thread
    int acc = 0;
    cum += v0.x; acc += cum < 0 ? -cum : cum;
    cum += v0.y; acc += cum < 0 ? -cum : cum;
    cum += v0.z; acc += cum < 0 ? -cum : cum;
    cum += v0.w; acc += cum < 0 ? -cum : cum;
    cum += v1.x; acc += cum < 0 ? -cum : cum;
    cum += v1.y; acc += cum < 0 ? -cum : cum;
    cum += v1.z; acc += cum < 0 ? -cum : cum;
    cum += v1.w; acc += cum < 0 ? -cum : cum;

    long long a = acc;
    #pragma unroll
    for (int d = 16; d; d >>= 1) a += __shfl_down_sync(0xffffffffu, a, d);
    if (lane == 0) wacc[w] = a;

    if (t < NC) atomicAdd(&sden, g_cnt[(t * BDIM + b) * R + (rb >> 2)]);
    __syncthreads();

    if (t == 0) {
        long long s = 0;
        #pragma unroll
        for (int i = 0; i < 32; i++) s += wacc[i];
        g_pnum[rb] = (double)s * (52.0 / (double)NBINS);
        g_pden[rb] = sden;
        __threadfence();

        int old = atomicAdd(&g_ticket, 1);
        if (old == RB - 1) {                  // last CTA: finalize
            g_ticket = 0;                     // self-reset for graph replays
            __threadfence();
            volatile double* vn = g_pnum;
            volatile int*    vd = g_pden;
            double ls = 0.0;
            int cv = 0;
            for (int bb = 0; bb < BDIM; bb++) {
                double num = 0.0; long long dn = 0;
                for (int r = 0; r < RB / BDIM; r++) {
                    num += vn[r * BDIM + bb];
                    dn  += vd[r * BDIM + bb];
                }
                if (dn > 0) {
                    ls += num / (double)(dn < 1 ? 1 : dn);
                    cv++;
                }
            }
            outp[0] = (float)(ls / (double)(cv > 0 ? cv : 1));
        }
    }
}

template <int RR>
static void launch_hist(const float* p, const float* g, const int* m, int V, int CH, int BV)
{
    int smem = RR * (NBINS / 2) * 4;
    cudaFuncSetAttribute(hist_kernel<RR>, cudaFuncAttributeMaxDynamicSharedMemorySize, smem);
    hist_kernel<RR><<<BDIM * NC, THREADS, smem>>>(p, g, m, V, CH, BV);
}

extern "C" void kernel_launch(void* const* d_in, const int* in_sizes, int n_in,
                              void* d_out, int out_size)
{
    const float* pred = (const float*)d_in[0];
    const float* tgt  = (const float*)d_in[1];
    const int*   mask = (const int*)d_in[2];

    int BV = in_sizes[0];                     // B*V = 4194304
    int V  = BV / BDIM;                       // 1048576
    int R  = in_sizes[2] / BV;                // 6
    int RB = R * BDIM;                        // 24
    int CH = ((V + NC - 1) / NC + 3) & ~3;    // chunk, multiple of 4

    switch (R) {
        case 1: launch_hist<1>(pred, tgt, mask, V, CH, BV); break;
        case 2: launch_hist<2>(pred, tgt, mask, V, CH, BV); break;
        case 3: launch_hist<3>(pred, tgt, mask, V, CH, BV); break;
        case 4: launch_hist<4>(pred, tgt, mask, V, CH, BV); break;
        case 5: launch_hist<5>(pred, tgt, mask, V, CH, BV); break;
        case 7: launch_hist<7>(pred, tgt, mask, V, CH, BV); break;
        default:
        case 6: launch_hist<6>(pred, tgt, mask, V, CH, BV); break;
    }
    merge_kernel<<<RB * SEGS, MTHR>>>(R, R * NBINS / 2);
    scan_kernel<<<RB, THREADS>>>((float*)d_out, R, RB);
}

// round 7
// speedup vs baseline: 1.4830x; 1.4830x over previous
#include <cuda_runtime.h>
#include <cstdint>

#define NBINS   8192
#define BDIM    4          // batch (fixed for this problem)
#define RMAX    7
#define NC      36         // chunks per batch image -> hist grid = 4*36 = 144
#define THREADS 1024

// Scratch (static device globals: allocation-free rule)
__device__ int    g_part16[BDIM * NC * RMAX * (NBINS / 2)]; // packed int16 pairs
__device__ int    g_cnt[BDIM * NC * RMAX];
__device__ double g_pnum[RMAX * BDIM];
__device__ int    g_pden[RMAX * BDIM];
__device__ int    g_ticket = 0;                             // self-resetting

__device__ __forceinline__ int binf(float x) {
    int k = __float2int_rz(x * (float)NBINS);
    return min(max(k, 0), NBINS - 1);
}

// One CTA: RR signed histograms (cntP - cntG), one chunk of one batch image.
// pred/tgt read ONCE (shared across all ROIs). smem = RR*NBINS*4 bytes. (R4 proven)
template <int RR>
__global__ void __launch_bounds__(THREADS, 1)
hist_kernel(const float* __restrict__ pred,
            const float* __restrict__ tgt,
            const int*   __restrict__ mask,   // bool serialized as int32, [R,B,V]
            int V, int CH)
{
    extern __shared__ int sh[];               // RR * NBINS signed counters
    __shared__ int scnt[RR];

    const int t = threadIdx.x;
    #pragma unroll
    for (int j = t; j < RR * NBINS; j += THREADS) sh[j] = 0;

    const int cid = blockIdx.x;
    const int b   = cid & (BDIM - 1);
    const int c   = cid >> 2;
    const size_t rstride = (size_t)BDIM * (size_t)V;

    const float* pp = pred + (size_t)b * V;
    const float* gp = tgt  + (size_t)b * V;
    const int*   mp = mask + (size_t)b * V;

    const int start = c * CH;
    const int end   = min(V, start + CH);

    int cnt[RR];
    #pragma unroll
    for (int r = 0; r < RR; r++) cnt[r] = 0;
    __syncthreads();

    for (int off = start + t * 4; off < end; off += THREADS * 4) {
        float4 pv = __ldcs(reinterpret_cast<const float4*>(pp + off));
        float4 gv = __ldcs(reinterpret_cast<const float4*>(gp + off));
        int4 mv[RR];
        #pragma unroll
        for (int r = 0; r < RR; r++)
            mv[r] = __ldcs(reinterpret_cast<const int4*>(mp + r * rstride + off));

        int p0 = binf(pv.x), p1 = binf(pv.y), p2 = binf(pv.z), p3 = binf(pv.w);
        int q0 = binf(gv.x), q1 = binf(gv.y), q2 = binf(gv.z), q3 = binf(gv.w);

        #pragma unroll
        for (int r = 0; r < RR; r++) {
            int* h = sh + r * NBINS;
            if (mv[r].x) { atomicAdd(h + p0, 1); atomicAdd(h + q0, -1); cnt[r]++; }
            if (mv[r].y) { atomicAdd(h + p1, 1); atomicAdd(h + q1, -1); cnt[r]++; }
            if (mv[r].z) { atomicAdd(h + p2, 1); atomicAdd(h + q2, -1); cnt[r]++; }
            if (mv[r].w) { atomicAdd(h + p3, 1); atomicAdd(h + q3, -1); cnt[r]++; }
        }
    }
    __syncthreads();
    if (t < RR) scnt[t] = 0;

    // flush: pack bin pairs into int (per-chunk counts provably fit int16)
    int* out = g_part16 + (size_t)cid * (RR * NBINS / 2);
    #pragma unroll
    for (int j = t; j < RR * NBINS / 2; j += THREADS)
        out[j] = (sh[2 * j] & 0xFFFF) | (sh[2 * j + 1] << 16);
    __syncthreads();

    #pragma unroll
    for (int r = 0; r < RR; r++) {
        int v = cnt[r];
        #pragma unroll
        for (int d = 16; d; d >>= 1) v += __shfl_down_sync(0xffffffffu, v, d);
        if ((t & 31) == 0 && v) atomicAdd(&scnt[r], v);
    }
    __syncthreads();
    if (t < RR) g_cnt[cid * RR + t] = scnt[t];
}

// Fused merge+scan: one CTA per (r,b). Thread t gathers its 8 consecutive bins
// [8t, 8t+8) directly from the NC packed partials (L2-resident), then the CTA
// prefix-scans 8192 bins and sums |cum|; the last-arriving CTA finalizes d_out.
__global__ void __launch_bounds__(THREADS, 1)
scan_kernel(float* __restrict__ outp, int R, int RB, int PACKN)
{
    __shared__ int wsum[33];
    __shared__ long long wacc[32];
    __shared__ int sden;

    int rb = blockIdx.x;
    int b  = rb & 3;
    int r  = rb >> 2;
    int t  = threadIdx.x, lane = t & 31, w = t >> 5;

    // merge: bins [8t, 8t+8) = packed ints [4t, 4t+4) of ROI r, summed over NC chunks
    const int* base = g_part16 + r * (NBINS / 2) + t * 4;
    int a0 = 0, a1 = 0, a2 = 0, a3 = 0, a4 = 0, a5 = 0, a6 = 0, a7 = 0;
    #pragma unroll 6
    for (int c = 0; c < NC; c++) {
        int4 v = *reinterpret_cast<const int4*>(base + (size_t)(c * BDIM + b) * PACKN);
        a0 += (int)(short)v.x; a1 += v.x >> 16;
        a2 += (int)(short)v.y; a3 += v.y >> 16;
        a4 += (int)(short)v.z; a5 += v.z >> 16;
        a6 += (int)(short)v.w; a7 += v.w >> 16;
    }

    int local = a0 + a1 + a2 + a3 + a4 + a5 + a6 + a7;

    int x = local;                            // warp inclusive scan
    #pragma unroll
    for (int d = 1; d < 32; d <<= 1) {
        int y = __shfl_up_sync(0xffffffffu, x, d);
        if (lane >= d) x += y;
    }
    if (lane == 31) wsum[w + 1] = x;
    if (t == 0) { sden = 0; wsum[0] = 0; }
    __syncthreads();
    if (t == 0)
        for (int i = 1; i < 32; i++) wsum[i + 1] += wsum[i];
    __syncthreads();

    int cum = wsum[w] + x - local;            // exclusive prefix for this thread
    int acc = 0;
    cum += a0; acc += cum < 0 ? -cum : cum;
    cum += a1; acc += cum < 0 ? -cum : cum;
    cum += a2; acc += cum < 0 ? -cum : cum;
    cum += a3; acc += cum < 0 ? -cum : cum;
    cum += a4; acc += cum < 0 ? -cum : cum;
    cum += a5; acc += cum < 0 ? -cum : cum;
    cum += a6; acc += cum < 0 ? -cum : cum;
    cum += a7; acc += cum < 0 ? -cum : cum;

    long long a = acc;
    #pragma unroll
    for (int d = 16; d; d >>= 1) a += __shfl_down_sync(0xffffffffu, a, d);
    if (lane == 0) wacc[w] = a;

    if (t < NC) atomicAdd(&sden, g_cnt[(t * BDIM + b) * R + r]);
    __syncthreads();

    if (t == 0) {
        long long s = 0;
        #pragma unroll
        for (int i = 0; i < 32; i++) s += wacc[i];
        g_pnum[rb] = (double)s * (52.0 / (double)NBINS);
        g_pden[rb] = sden;
        __threadfence();

        int old = atomicAdd(&g_ticket, 1);
        if (old == RB - 1) {                  // last CTA: finalize
            g_ticket = 0;                     // self-reset for graph replays
            __threadfence();
            volatile double* vn = g_pnum;
            volatile int*    vd = g_pden;
            double ls = 0.0;
            int cv = 0;
            for (int bb = 0; bb < BDIM; bb++) {
                double num = 0.0; long long dn = 0;
                for (int rr = 0; rr < RB / BDIM; rr++) {
                    num += vn[rr * BDIM + bb];
                    dn  += vd[rr * BDIM + bb];
                }
                if (dn > 0) {
                    ls += num / (double)(dn < 1 ? 1 : dn);
                    cv++;
                }
            }
            outp[0] = (float)(ls / (double)(cv > 0 ? cv : 1));
        }
    }
}

template <int RR>
static void launch_hist(const float* p, const float* g, const int* m, int V, int CH)
{
    int smem = RR * NBINS * 4;
    cudaFuncSetAttribute(hist_kernel<RR>, cudaFuncAttributeMaxDynamicSharedMemorySize, smem);
    hist_kernel<RR><<<BDIM * NC, THREADS, smem>>>(p, g, m, V, CH);
}

extern "C" void kernel_launch(void* const* d_in, const int* in_sizes, int n_in,
                              void* d_out, int out_size)
{
    const float* pred = (const float*)d_in[0];
    const float* tgt  = (const float*)d_in[1];
    const int*   mask = (const int*)d_in[2];

    int BV = in_sizes[0];                     // B*V = 4194304
    int V  = BV / BDIM;                       // 1048576
    int R  = in_sizes[2] / BV;                // 6
    int RB = R * BDIM;                        // 24
    int CH = ((V + NC - 1) / NC + 3) & ~3;    // chunk, multiple of 4

    switch (R) {
        case 1: launch_hist<1>(pred, tgt, mask, V, CH); break;
        case 2: launch_hist<2>(pred, tgt, mask, V, CH); break;
        case 3: launch_hist<3>(pred, tgt, mask, V, CH); break;
        case 4: launch_hist<4>(pred, tgt, mask, V, CH); break;
        case 5: launch_hist<5>(pred, tgt, mask, V, CH); break;
        case 7: launch_hist<7>(pred, tgt, mask, V, CH); break;
        default:
        case 6: launch_hist<6>(pred, tgt, mask, V, CH); break;
    }
    scan_kernel<<<RB, THREADS>>>((float*)d_out, R, RB, R * NBINS / 2);
}